// round 6
// baseline (speedup 1.0000x reference)
#include <cuda_runtime.h>
#include <cuda_bf16.h>
#include <math.h>

#define BB 4
#define C 64
#define C2 128
#define H 128
#define W 128
#define HW (H*W)
#define FIELD_N (BB*C*HW)
#define TILE_H 8
#define TILE_W 16
#define NT 256
#define NCTA 256
#define TILES 512
#define MAX_STEPS 50
#define DT_C 0.1f
#define THRESH_C 0.01

// ---- smem byte offsets ----
#define SM_SF   0          // 64*180*4 = 46080 fp32 halo
#define SM_W1H  46080      // 16384 (128 rows x 32 u32, pair-swizzled)
#define SM_W1L  62464
#define SM_W2H  78848      // 16384 (64 rows x 64 u32, pair-swizzled)
#define SM_W2L  95232
#define SM_B1   111616     // 512
#define SM_B2   112128     // 256
#define SM_DB   112384     // 256
#define SM_DW   112640     // 2304
#define SM_RED  114944     // 64
#define SMEM_BYTES 115008

typedef unsigned u32;
typedef unsigned short u16;

__device__ __forceinline__ u32 pack_bf16x2(float lo, float hi) {
    __nv_bfloat162 t = __floats2bfloat162_rn(lo, hi);
    return *reinterpret_cast<u32*>(&t);
}

__device__ __forceinline__ void mma_bf16(float* d, const u32* a, u32 b0, u32 b1) {
    asm volatile(
        "mma.sync.aligned.m16n8k16.row.col.f32.bf16.bf16.f32 "
        "{%0,%1,%2,%3}, {%4,%5,%6,%7}, {%8,%9}, {%0,%1,%2,%3};"
        : "+f"(d[0]), "+f"(d[1]), "+f"(d[2]), "+f"(d[3])
        : "r"(a[0]), "r"(a[1]), "r"(a[2]), "r"(a[3]), "r"(b0), "r"(b1));
}

__device__ float g_buf0[FIELD_N];
__device__ float g_buf1[FIELD_N];
__device__ volatile int      g_done;
__device__ int               g_steps;
__device__ int               g_cur;
__device__ double            g_sum;
__device__ unsigned          g_barc;
__device__ volatile unsigned g_phase;
// pair-swizzled bf16 hi/lo weight words (u32 = bf16x2)
__device__ __align__(16) u32 g_w1h[4096];
__device__ __align__(16) u32 g_w1l[4096];
__device__ __align__(16) u32 g_w2h[4096];
__device__ __align__(16) u32 g_w2l[4096];

__global__ void afe_init_kernel(const float* __restrict__ field) {
    int tid = blockIdx.x * blockDim.x + threadIdx.x;
    if (tid == 0) {
        g_done = 0; g_steps = 0; g_cur = 0; g_sum = 0.0;
        g_barc = 0u; g_phase = 0u;
    }
    int stride = gridDim.x * blockDim.x;
    for (int i = tid; i < FIELD_N; i += stride) g_buf0[i] = field[i];
}

__global__ void afe_prep_weights(const float* __restrict__ w1, const float* __restrict__ w2) {
    int tid = blockIdx.x * blockDim.x + threadIdx.x;
    int stride = gridDim.x * blockDim.x;
    // w1 [j=128][c=64]: bf16 word wlog = c>>1 = 8kc + t4 + 4q
    // store word pair (w, w+4) adjacent: u32 idx = j*32 + ((4kc+t4)*2 ^ ((j&3)<<3)) + q
    for (int i = tid; i < C2 * 32; i += stride) {   // i = j*32 + wlog
        int j = i >> 5, wlog = i & 31;
        int kc = wlog >> 3, rem = wlog & 7;
        int q = rem >> 2, t4 = rem & 3;
        int c = 2 * wlog;
        float v0 = w1[j * C + c], v1 = w1[j * C + c + 1];
        __nv_bfloat16 h0 = __float2bfloat16_rn(v0), h1 = __float2bfloat16_rn(v1);
        float l0 = v0 - __bfloat162float(h0), l1 = v1 - __bfloat162float(h1);
        int idx = j * 32 + (((kc * 4 + t4) * 2) ^ ((j & 3) << 3)) + q;
        g_w1h[idx] = pack_bf16x2(__bfloat162float(h0), __bfloat162float(h1));
        g_w1l[idx] = pack_bf16x2(l0, l1);
    }
    // w2 [c=64][j=128]: wlog = j>>1 = 8kc + t4 + 4q (kc 0..7)
    // u32 idx = c*64 + ((kc*8 + t4*2) ^ ((c&3)<<3)) + q
    for (int i = tid; i < C * 64; i += stride) {    // i = c*64 + wlog
        int cc = i >> 6, wlog = i & 63;
        int kc = wlog >> 3, rem = wlog & 7;
        int q = rem >> 2, t4 = rem & 3;
        int j = 2 * wlog;
        float v0 = w2[cc * C2 + j], v1 = w2[cc * C2 + j + 1];
        __nv_bfloat16 h0 = __float2bfloat16_rn(v0), h1 = __float2bfloat16_rn(v1);
        float l0 = v0 - __bfloat162float(h0), l1 = v1 - __bfloat162float(h1);
        int idx = cc * 64 + ((kc * 8 + t4 * 2) ^ ((cc & 3) << 3)) + q;
        g_w2h[idx] = pack_bf16x2(__bfloat162float(h0), __bfloat162float(h1));
        g_w2l[idx] = pack_bf16x2(l0, l1);
    }
}

__global__ __launch_bounds__(NT, 2)
void afe_persist_kernel(const float* __restrict__ dw, const float* __restrict__ db,
                        const float* __restrict__ b1, const float* __restrict__ b2,
                        const float* __restrict__ dcoeff) {
    extern __shared__ char smc[];
    float* sf  = (float*)(smc + SM_SF);
    u32* sW1h = (u32*)(smc + SM_W1H);
    u32* sW1l = (u32*)(smc + SM_W1L);
    u32* sW2h = (u32*)(smc + SM_W2H);
    u32* sW2l = (u32*)(smc + SM_W2L);
    float* sb1 = (float*)(smc + SM_B1);
    float* sb2 = (float*)(smc + SM_B2);
    float* sdb = (float*)(smc + SM_DB);
    float* sdw = (float*)(smc + SM_DW);
    float* sred = (float*)(smc + SM_RED);
    int* sflag = (int*)(smc + SM_RED + 32);

    const int tid = threadIdx.x;
    const int wwid = tid >> 5;
    const int lane = tid & 31;
    const int g2 = lane >> 2;
    const int t4 = lane & 3;

    // ---- stage weights/biases ONCE ----
    {
        uint4* d0 = (uint4*)sW1h; const uint4* s0 = (const uint4*)g_w1h;
        uint4* d1 = (uint4*)sW1l; const uint4* s1 = (const uint4*)g_w1l;
        uint4* d2 = (uint4*)sW2h; const uint4* s2 = (const uint4*)g_w2h;
        uint4* d3 = (uint4*)sW2l; const uint4* s3 = (const uint4*)g_w2l;
        #pragma unroll
        for (int i = tid; i < 1024; i += NT) {
            d0[i] = s0[i]; d1[i] = s1[i]; d2[i] = s2[i]; d3[i] = s3[i];
        }
    }
    if (tid < C2) sb1[tid] = b1[tid];
    if (tid < C)  { sb2[tid] = b2[tid]; sdb[tid] = db[tid]; }
    for (int i = tid; i < C * 9; i += NT) sdw[i] = dw[i];
    const float dc = __ldg(dcoeff);
    __syncthreads();

    int cur = 0;
    for (int step = 0; step < MAX_STEPS; step++) {
        const float* fin  = cur ? g_buf1 : g_buf0;
        float*       fout = cur ? g_buf0 : g_buf1;
        float lsum = 0.0f;

        #pragma unroll
        for (int tl = 0; tl < 2; tl++) {
            const int t  = blockIdx.x + tl * NCTA;
            const int b  = t >> 7;
            const int y0 = ((t >> 3) & 15) * TILE_H;
            const int x0 = (t & 7) * TILE_W;

            // ---- fp32 halo tile [64][10][18], zero-pad SAME ----
            for (int i = tid; i < C * 180; i += NT) {
                int c  = i / 180;
                int rr = (i % 180) / 18;
                int xx = i % 18;
                int y = y0 - 1 + rr;
                int x = x0 - 1 + xx;
                float v = 0.0f;
                if (y >= 0 && y < H && x >= 0 && x < W)
                    v = fin[((b * C + c) * H + y) * W + x];
                sf[i] = v;
            }
            __syncthreads();

            // ---- A1 fragments in registers from sf ----
            u32 ah[4][4], al[4][4];
            {
                const int pr = (wwid + 1) * 18 + 1;
                #pragma unroll
                for (int kc = 0; kc < 4; kc++) {
                    #pragma unroll
                    for (int q = 0; q < 2; q++) {
                        int c = 16 * kc + 2 * t4 + 8 * q;
                        float v00 = sf[c * 180 + pr + g2];
                        float v01 = sf[(c + 1) * 180 + pr + g2];
                        float v10 = sf[c * 180 + pr + g2 + 8];
                        float v11 = sf[(c + 1) * 180 + pr + g2 + 8];
                        __nv_bfloat16 h00 = __float2bfloat16_rn(v00);
                        __nv_bfloat16 h01 = __float2bfloat16_rn(v01);
                        __nv_bfloat16 h10 = __float2bfloat16_rn(v10);
                        __nv_bfloat16 h11 = __float2bfloat16_rn(v11);
                        ah[kc][2 * q]     = pack_bf16x2(__bfloat162float(h00), __bfloat162float(h01));
                        ah[kc][2 * q + 1] = pack_bf16x2(__bfloat162float(h10), __bfloat162float(h11));
                        al[kc][2 * q]     = pack_bf16x2(v00 - __bfloat162float(h00), v01 - __bfloat162float(h01));
                        al[kc][2 * q + 1] = pack_bf16x2(v10 - __bfloat162float(h10), v11 - __bfloat162float(h11));
                    }
                }
            }

            // ---- GEMM1 (two N-halves) + gelu -> GEMM2 A fragments ----
            u32 a2h[8][4], a2l[8][4];
            #pragma unroll
            for (int hh = 0; hh < 2; hh++) {
                float acc[8][4];
                #pragma unroll
                for (int ntl = 0; ntl < 8; ntl++)
                    #pragma unroll
                    for (int e = 0; e < 4; e++) acc[ntl][e] = 0.0f;

                #pragma unroll
                for (int ntl = 0; ntl < 8; ntl++) {
                    const int row = 8 * (8 * hh + ntl) + g2;
                    const int rbase = row * 32;
                    const int swz = (row & 3) << 3;
                    #pragma unroll
                    for (int kc = 0; kc < 4; kc++) {
                        int off = rbase + (((kc * 4 + t4) * 2) ^ swz);
                        uint2 bh = *(const uint2*)(sW1h + off);
                        uint2 bl = *(const uint2*)(sW1l + off);
                        mma_bf16(acc[ntl], ah[kc], bh.x, bh.y);
                        mma_bf16(acc[ntl], ah[kc], bl.x, bl.y);
                        mma_bf16(acc[ntl], al[kc], bh.x, bh.y);
                    }
                }

                #pragma unroll
                for (int ntl = 0; ntl < 8; ntl++) {
                    const int n = 8 * hh + ntl;
                    float bias0 = sb1[8 * n + 2 * t4];
                    float bias1 = sb1[8 * n + 2 * t4 + 1];
                    float x0 = acc[ntl][0] + bias0;
                    float x1 = acc[ntl][1] + bias1;
                    float x2 = acc[ntl][2] + bias0;
                    float x3 = acc[ntl][3] + bias1;
                    float gl0 = 0.5f * x0 * (1.0f + erff(x0 * 0.70710678118654752f));
                    float gl1 = 0.5f * x1 * (1.0f + erff(x1 * 0.70710678118654752f));
                    float gl2 = 0.5f * x2 * (1.0f + erff(x2 * 0.70710678118654752f));
                    float gl3 = 0.5f * x3 * (1.0f + erff(x3 * 0.70710678118654752f));
                    __nv_bfloat16 h0 = __float2bfloat16_rn(gl0);
                    __nv_bfloat16 h1 = __float2bfloat16_rn(gl1);
                    __nv_bfloat16 h2 = __float2bfloat16_rn(gl2);
                    __nv_bfloat16 h3 = __float2bfloat16_rn(gl3);
                    int kc2 = n >> 1;
                    int q  = (n & 1) << 1;
                    a2h[kc2][q]     = pack_bf16x2(__bfloat162float(h0), __bfloat162float(h1));
                    a2h[kc2][q + 1] = pack_bf16x2(__bfloat162float(h2), __bfloat162float(h3));
                    a2l[kc2][q]     = pack_bf16x2(gl0 - __bfloat162float(h0), gl1 - __bfloat162float(h1));
                    a2l[kc2][q + 1] = pack_bf16x2(gl2 - __bfloat162float(h2), gl3 - __bfloat162float(h3));
                }
            }

            // ---- GEMM2 ----
            float acc2[8][4];
            #pragma unroll
            for (int nt = 0; nt < 8; nt++)
                #pragma unroll
                for (int e = 0; e < 4; e++) acc2[nt][e] = 0.0f;

            #pragma unroll
            for (int nt = 0; nt < 8; nt++) {
                const int row = 8 * nt + g2;
                const int rbase = row * 64;
                const int swz = (row & 3) << 3;
                #pragma unroll
                for (int kc = 0; kc < 8; kc++) {
                    int off = rbase + ((kc * 8 + t4 * 2) ^ swz);
                    uint2 bh = *(const uint2*)(sW2h + off);
                    uint2 bl = *(const uint2*)(sW2l + off);
                    mma_bf16(acc2[nt], a2h[kc], bh.x, bh.y);
                    mma_bf16(acc2[nt], a2h[kc], bl.x, bl.y);
                    mma_bf16(acc2[nt], a2l[kc], bh.x, bh.y);
                }
            }

            // ---- epilogue: depthwise + Euler + |delta| ----
            #pragma unroll
            for (int nt = 0; nt < 8; nt++) {
                #pragma unroll
                for (int e = 0; e < 2; e++) {
                    const int c = 8 * nt + 2 * t4 + e;
                    const float* base = sf + c * 180;
                    const float wd0 = sdw[c * 9 + 0], wd1 = sdw[c * 9 + 1], wd2 = sdw[c * 9 + 2];
                    const float wd3 = sdw[c * 9 + 3], wd4 = sdw[c * 9 + 4], wd5 = sdw[c * 9 + 5];
                    const float wd6 = sdw[c * 9 + 6], wd7 = sdw[c * 9 + 7], wd8 = sdw[c * 9 + 8];
                    const float bias2 = sb2[c];
                    const float dbv = sdb[c];
                    #pragma unroll
                    for (int half = 0; half < 2; half++) {
                        const int col = g2 + 8 * half;
                        float s;
                        s = wd0 * base[(wwid + 0) * 18 + col + 0];
                        s = fmaf(wd1, base[(wwid + 0) * 18 + col + 1], s);
                        s = fmaf(wd2, base[(wwid + 0) * 18 + col + 2], s);
                        s = fmaf(wd3, base[(wwid + 1) * 18 + col + 0], s);
                        s = fmaf(wd4, base[(wwid + 1) * 18 + col + 1], s);
                        s = fmaf(wd5, base[(wwid + 1) * 18 + col + 2], s);
                        s = fmaf(wd6, base[(wwid + 2) * 18 + col + 0], s);
                        s = fmaf(wd7, base[(wwid + 2) * 18 + col + 1], s);
                        s = fmaf(wd8, base[(wwid + 2) * 18 + col + 2], s);
                        float react = acc2[nt][2 * half + e] + bias2;
                        float deriv = dc * (s + dbv) + react;
                        float fold = base[(wwid + 1) * 18 + col + 1];
                        float fnew = fmaf(DT_C, deriv, fold);
                        lsum += fabsf(fnew - fold);
                        fout[((b * C + c) * H + (y0 + wwid)) * W + (x0 + col)] = fnew;
                    }
                }
            }
            __syncthreads();   // sf reuse / next tile
        }

        // ---- CTA reduce ----
        #pragma unroll
        for (int off = 16; off > 0; off >>= 1)
            lsum += __shfl_xor_sync(0xFFFFFFFFu, lsum, off);
        if (lane == 0) sred[wwid] = lsum;
        __threadfence();       // publish this thread's field writes
        __syncthreads();

        // ---- grid barrier; closer finalizes step ----
        if (tid == 0) {
            float bs = 0.0f;
            #pragma unroll
            for (int i = 0; i < 8; i++) bs += sred[i];
            atomicAdd(&g_sum, (double)bs);
            __threadfence();
            unsigned prev = atomicAdd(&g_barc, 1u);
            if (prev == NCTA - 1) {
                __threadfence();
                double mean = g_sum / (double)FIELD_N;
                g_steps += 1;
                if (mean < THRESH_C) g_done = 1;
                g_cur ^= 1;
                g_sum = 0.0;
                g_barc = 0u;
                __threadfence();
                g_phase = (unsigned)(step + 1);
            } else {
                while (g_phase <= (unsigned)step) __nanosleep(64);
            }
            __threadfence();
            *sflag = g_done;
        }
        __syncthreads();
        if (*sflag) break;
        cur ^= 1;
    }
}

__global__ void afe_output_kernel(float* __restrict__ out, int out_size) {
    const float* f = g_cur ? g_buf1 : g_buf0;
    int tid = blockIdx.x * blockDim.x + threadIdx.x;
    int stride = gridDim.x * blockDim.x;
    float stepsf = (float)g_steps;
    for (int i = tid; i < out_size; i += stride)
        out[i] = (i < FIELD_N) ? f[i] : stepsf;
}

extern "C" void kernel_launch(void* const* d_in, const int* in_sizes, int n_in,
                              void* d_out, int out_size) {
    const float* field  = (const float*)d_in[0];
    const float* dw     = (const float*)d_in[1];
    const float* db     = (const float*)d_in[2];
    const float* w1     = (const float*)d_in[3];
    const float* b1     = (const float*)d_in[4];
    const float* w2     = (const float*)d_in[5];
    const float* b2     = (const float*)d_in[6];
    const float* dcoeff = (const float*)d_in[7];

    cudaFuncSetAttribute(afe_persist_kernel,
                         cudaFuncAttributeMaxDynamicSharedMemorySize, SMEM_BYTES);

    afe_init_kernel<<<1024, 256>>>(field);
    afe_prep_weights<<<64, 256>>>(w1, w2);
    afe_persist_kernel<<<NCTA, NT, SMEM_BYTES>>>(dw, db, b1, b2, dcoeff);
    afe_output_kernel<<<2048, 256>>>((float*)d_out, out_size);
}

// round 7
// speedup vs baseline: 1.1368x; 1.1368x over previous
#include <cuda_runtime.h>
#include <cuda_bf16.h>
#include <math.h>

#define BB 4
#define C 64
#define C2 128
#define H 128
#define W 128
#define HW (H*W)
#define FIELD_N (BB*C*HW)
#define TILE_H 8
#define TILE_W 16
#define NT 256
#define NBLK 512
#define MAX_STEPS 50
#define DT_C 0.1f
#define THRESH_C 0.01

// ---- smem byte offsets ----
#define SM_SF   0          // 64*180*4 = 46080 fp32 halo
#define SM_W1H  46080      // 16384 (128 rows x 32 u32, pair-swizzled)
#define SM_W1L  62464
#define SM_W2H  78848      // 16384 (64 rows x 64 u32, pair-swizzled)
#define SM_W2L  95232
#define SM_B1   111616     // 512
#define SM_B2   112128     // 256
#define SM_DB   112384     // 256
#define SM_DW   112640     // 2304
#define SM_RED  114944     // 32
#define SMEM_BYTES 114976

typedef unsigned u32;
typedef unsigned short u16;

__device__ __forceinline__ u32 pack_bf16x2(float lo, float hi) {
    __nv_bfloat162 t = __floats2bfloat162_rn(lo, hi);
    return *reinterpret_cast<u32*>(&t);
}

__device__ __forceinline__ void mma_bf16(float* d, const u32* a, u32 b0, u32 b1) {
    asm volatile(
        "mma.sync.aligned.m16n8k16.row.col.f32.bf16.bf16.f32 "
        "{%0,%1,%2,%3}, {%4,%5,%6,%7}, {%8,%9}, {%0,%1,%2,%3};"
        : "+f"(d[0]), "+f"(d[1]), "+f"(d[2]), "+f"(d[3])
        : "r"(a[0]), "r"(a[1]), "r"(a[2]), "r"(a[3]), "r"(b0), "r"(b1));
}

// gelu(x) with A&S 7.1.26 erf approximation, |erf err| <= 1.5e-7 abs
__device__ __forceinline__ float gelu_f(float x) {
    float ax = fabsf(x) * 0.70710678118654752f;
    float t = __fdividef(1.0f, fmaf(0.3275911f, ax, 1.0f));
    float poly = t * fmaf(t, fmaf(t, fmaf(t, fmaf(t, 1.061405429f, -1.453152027f),
                                          1.421413741f), -0.284496736f), 0.254829592f);
    float e = __expf(-ax * ax);
    float er = fmaf(-poly, e, 1.0f);
    er = copysignf(er, x);
    return 0.5f * x * (1.0f + er);
}

__device__ float g_buf0[FIELD_N];
__device__ float g_buf1[FIELD_N];
__device__ int      g_done;
__device__ int      g_steps;
__device__ int      g_cur;
__device__ double   g_sum;
__device__ unsigned g_count;
// pair-swizzled bf16 hi/lo weight words (u32 = bf16x2)
__device__ __align__(16) u32 g_w1h[4096];
__device__ __align__(16) u32 g_w1l[4096];
__device__ __align__(16) u32 g_w2h[4096];
__device__ __align__(16) u32 g_w2l[4096];

__global__ void afe_init_kernel(const float* __restrict__ field) {
    int tid = blockIdx.x * blockDim.x + threadIdx.x;
    if (tid == 0) { g_done = 0; g_steps = 0; g_cur = 0; g_sum = 0.0; g_count = 0u; }
    int stride = gridDim.x * blockDim.x;
    for (int i = tid; i < FIELD_N; i += stride) g_buf0[i] = field[i];
}

__global__ void afe_prep_weights(const float* __restrict__ w1, const float* __restrict__ w2) {
    int tid = blockIdx.x * blockDim.x + threadIdx.x;
    int stride = gridDim.x * blockDim.x;
    // w1 [j=128][c=64]: word wlog = c>>1 = 8kc + t4 + 4q
    // u32 idx = j*32 + (((4kc+t4)*2) ^ ((j&3)<<3)) + q
    for (int i = tid; i < C2 * 32; i += stride) {
        int j = i >> 5, wlog = i & 31;
        int kc = wlog >> 3, rem = wlog & 7;
        int q = rem >> 2, t4 = rem & 3;
        int c = 2 * wlog;
        float v0 = w1[j * C + c], v1 = w1[j * C + c + 1];
        __nv_bfloat16 h0 = __float2bfloat16_rn(v0), h1 = __float2bfloat16_rn(v1);
        float l0 = v0 - __bfloat162float(h0), l1 = v1 - __bfloat162float(h1);
        int idx = j * 32 + (((kc * 4 + t4) * 2) ^ ((j & 3) << 3)) + q;
        g_w1h[idx] = pack_bf16x2(__bfloat162float(h0), __bfloat162float(h1));
        g_w1l[idx] = pack_bf16x2(l0, l1);
    }
    // w2 [c=64][j=128]: wlog = j>>1 = 8kc + t4 + 4q (kc 0..7)
    // u32 idx = c*64 + ((kc*8 + t4*2) ^ ((c&3)<<3)) + q
    for (int i = tid; i < C * 64; i += stride) {
        int cc = i >> 6, wlog = i & 63;
        int kc = wlog >> 3, rem = wlog & 7;
        int q = rem >> 2, t4 = rem & 3;
        int j = 2 * wlog;
        float v0 = w2[cc * C2 + j], v1 = w2[cc * C2 + j + 1];
        __nv_bfloat16 h0 = __float2bfloat16_rn(v0), h1 = __float2bfloat16_rn(v1);
        float l0 = v0 - __bfloat162float(h0), l1 = v1 - __bfloat162float(h1);
        int idx = cc * 64 + ((kc * 8 + t4 * 2) ^ ((cc & 3) << 3)) + q;
        g_w2h[idx] = pack_bf16x2(__bfloat162float(h0), __bfloat162float(h1));
        g_w2l[idx] = pack_bf16x2(l0, l1);
    }
}

__global__ __launch_bounds__(NT, 2)
void afe_step_kernel(const float* __restrict__ dw, const float* __restrict__ db,
                     const float* __restrict__ b1, const float* __restrict__ b2,
                     const float* __restrict__ dcoeff) {
    if (g_done) return;

    extern __shared__ char smc[];
    float* sf  = (float*)(smc + SM_SF);
    u32* sW1h = (u32*)(smc + SM_W1H);
    u32* sW1l = (u32*)(smc + SM_W1L);
    u32* sW2h = (u32*)(smc + SM_W2H);
    u32* sW2l = (u32*)(smc + SM_W2L);
    float* sb1 = (float*)(smc + SM_B1);
    float* sb2 = (float*)(smc + SM_B2);
    float* sdb = (float*)(smc + SM_DB);
    float* sdw = (float*)(smc + SM_DW);
    float* sred = (float*)(smc + SM_RED);

    const float* fin  = g_cur ? g_buf1 : g_buf0;
    float*       fout = g_cur ? g_buf0 : g_buf1;

    const int b  = blockIdx.z;
    const int y0 = blockIdx.y * TILE_H;
    const int x0 = blockIdx.x * TILE_W;
    const int tid = threadIdx.x;
    const int wwid = tid >> 5;
    const int lane = tid & 31;
    const int g2 = lane >> 2;
    const int t4 = lane & 3;

    // ---- stage weights (linear uint4 copies; pre-swizzled in gmem) ----
    {
        uint4* d0 = (uint4*)sW1h; const uint4* s0 = (const uint4*)g_w1h;
        uint4* d1 = (uint4*)sW1l; const uint4* s1 = (const uint4*)g_w1l;
        uint4* d2 = (uint4*)sW2h; const uint4* s2 = (const uint4*)g_w2h;
        uint4* d3 = (uint4*)sW2l; const uint4* s3 = (const uint4*)g_w2l;
        #pragma unroll
        for (int i = tid; i < 1024; i += NT) {
            d0[i] = s0[i]; d1[i] = s1[i]; d2[i] = s2[i]; d3[i] = s3[i];
        }
    }
    if (tid < C2) sb1[tid] = b1[tid];
    if (tid < C)  { sb2[tid] = b2[tid]; sdb[tid] = db[tid]; }
    for (int i = tid; i < C * 9; i += NT) sdw[i] = dw[i];

    // ---- fp32 halo tile [64][10][18], zero-pad SAME ----
    for (int i = tid; i < C * 180; i += NT) {
        int c  = i / 180;
        int rr = (i % 180) / 18;
        int xx = i % 18;
        int y = y0 - 1 + rr;
        int x = x0 - 1 + xx;
        float v = 0.0f;
        if (y >= 0 && y < H && x >= 0 && x < W)
            v = fin[((b * C + c) * H + y) * W + x];
        sf[i] = v;
    }
    __syncthreads();

    // ---- A1 fragments in registers straight from sf ----
    u32 ah[4][4], al[4][4];
    {
        const int pr = (wwid + 1) * 18 + 1;
        #pragma unroll
        for (int kc = 0; kc < 4; kc++) {
            #pragma unroll
            for (int q = 0; q < 2; q++) {
                int c = 16 * kc + 2 * t4 + 8 * q;
                float v00 = sf[c * 180 + pr + g2];
                float v01 = sf[(c + 1) * 180 + pr + g2];
                float v10 = sf[c * 180 + pr + g2 + 8];
                float v11 = sf[(c + 1) * 180 + pr + g2 + 8];
                __nv_bfloat16 h00 = __float2bfloat16_rn(v00);
                __nv_bfloat16 h01 = __float2bfloat16_rn(v01);
                __nv_bfloat16 h10 = __float2bfloat16_rn(v10);
                __nv_bfloat16 h11 = __float2bfloat16_rn(v11);
                ah[kc][2 * q]     = pack_bf16x2(__bfloat162float(h00), __bfloat162float(h01));
                ah[kc][2 * q + 1] = pack_bf16x2(__bfloat162float(h10), __bfloat162float(h11));
                al[kc][2 * q]     = pack_bf16x2(v00 - __bfloat162float(h00), v01 - __bfloat162float(h01));
                al[kc][2 * q + 1] = pack_bf16x2(v10 - __bfloat162float(h10), v11 - __bfloat162float(h11));
            }
        }
    }

    // ---- GEMM1 (two N-halves) + gelu -> GEMM2 A fragments ----
    u32 a2h[8][4], a2l[8][4];
    #pragma unroll
    for (int hh = 0; hh < 2; hh++) {
        float acc[8][4];
        #pragma unroll
        for (int ntl = 0; ntl < 8; ntl++)
            #pragma unroll
            for (int e = 0; e < 4; e++) acc[ntl][e] = 0.0f;

        #pragma unroll
        for (int ntl = 0; ntl < 8; ntl++) {
            const int row = 8 * (8 * hh + ntl) + g2;
            const int rbase = row * 32;
            const int swz = (row & 3) << 3;
            #pragma unroll
            for (int kc = 0; kc < 4; kc++) {
                int off = rbase + (((kc * 4 + t4) * 2) ^ swz);
                uint2 bh = *(const uint2*)(sW1h + off);
                uint2 bl = *(const uint2*)(sW1l + off);
                mma_bf16(acc[ntl], ah[kc], bh.x, bh.y);
                mma_bf16(acc[ntl], ah[kc], bl.x, bl.y);
                mma_bf16(acc[ntl], al[kc], bh.x, bh.y);
            }
        }

        #pragma unroll
        for (int ntl = 0; ntl < 8; ntl++) {
            const int n = 8 * hh + ntl;
            float bias0 = sb1[8 * n + 2 * t4];
            float bias1 = sb1[8 * n + 2 * t4 + 1];
            float gl0 = gelu_f(acc[ntl][0] + bias0);
            float gl1 = gelu_f(acc[ntl][1] + bias1);
            float gl2 = gelu_f(acc[ntl][2] + bias0);
            float gl3 = gelu_f(acc[ntl][3] + bias1);
            __nv_bfloat16 h0 = __float2bfloat16_rn(gl0);
            __nv_bfloat16 h1 = __float2bfloat16_rn(gl1);
            __nv_bfloat16 h2 = __float2bfloat16_rn(gl2);
            __nv_bfloat16 h3 = __float2bfloat16_rn(gl3);
            int kc2 = n >> 1;
            int q  = (n & 1) << 1;
            a2h[kc2][q]     = pack_bf16x2(__bfloat162float(h0), __bfloat162float(h1));
            a2h[kc2][q + 1] = pack_bf16x2(__bfloat162float(h2), __bfloat162float(h3));
            a2l[kc2][q]     = pack_bf16x2(gl0 - __bfloat162float(h0), gl1 - __bfloat162float(h1));
            a2l[kc2][q + 1] = pack_bf16x2(gl2 - __bfloat162float(h2), gl3 - __bfloat162float(h3));
        }
    }

    // ---- GEMM2 ----
    float acc2[8][4];
    #pragma unroll
    for (int nt = 0; nt < 8; nt++)
        #pragma unroll
        for (int e = 0; e < 4; e++) acc2[nt][e] = 0.0f;

    #pragma unroll
    for (int nt = 0; nt < 8; nt++) {
        const int row = 8 * nt + g2;
        const int rbase = row * 64;
        const int swz = (row & 3) << 3;
        #pragma unroll
        for (int kc = 0; kc < 8; kc++) {
            int off = rbase + ((kc * 8 + t4 * 2) ^ swz);
            uint2 bh = *(const uint2*)(sW2h + off);
            uint2 bl = *(const uint2*)(sW2l + off);
            mma_bf16(acc2[nt], a2h[kc], bh.x, bh.y);
            mma_bf16(acc2[nt], a2h[kc], bl.x, bl.y);
            mma_bf16(acc2[nt], a2l[kc], bh.x, bh.y);
        }
    }

    // ---- epilogue: depthwise + Euler + |delta| ----
    const float dc = __ldg(dcoeff);
    float lsum = 0.0f;
    #pragma unroll
    for (int nt = 0; nt < 8; nt++) {
        #pragma unroll
        for (int e = 0; e < 2; e++) {
            const int c = 8 * nt + 2 * t4 + e;
            const float* base = sf + c * 180;
            const float wd0 = sdw[c * 9 + 0], wd1 = sdw[c * 9 + 1], wd2 = sdw[c * 9 + 2];
            const float wd3 = sdw[c * 9 + 3], wd4 = sdw[c * 9 + 4], wd5 = sdw[c * 9 + 5];
            const float wd6 = sdw[c * 9 + 6], wd7 = sdw[c * 9 + 7], wd8 = sdw[c * 9 + 8];
            const float bias2 = sb2[c];
            const float dbv = sdb[c];
            #pragma unroll
            for (int half = 0; half < 2; half++) {
                const int col = g2 + 8 * half;
                float s;
                s = wd0 * base[(wwid + 0) * 18 + col + 0];
                s = fmaf(wd1, base[(wwid + 0) * 18 + col + 1], s);
                s = fmaf(wd2, base[(wwid + 0) * 18 + col + 2], s);
                s = fmaf(wd3, base[(wwid + 1) * 18 + col + 0], s);
                s = fmaf(wd4, base[(wwid + 1) * 18 + col + 1], s);
                s = fmaf(wd5, base[(wwid + 1) * 18 + col + 2], s);
                s = fmaf(wd6, base[(wwid + 2) * 18 + col + 0], s);
                s = fmaf(wd7, base[(wwid + 2) * 18 + col + 1], s);
                s = fmaf(wd8, base[(wwid + 2) * 18 + col + 2], s);
                float react = acc2[nt][2 * half + e] + bias2;
                float deriv = dc * (s + dbv) + react;
                float fold = base[(wwid + 1) * 18 + col + 1];
                float fnew = fmaf(DT_C, deriv, fold);
                lsum += fabsf(fnew - fold);
                fout[((b * C + c) * H + (y0 + wwid)) * W + (x0 + col)] = fnew;
            }
        }
    }

    // ---- reduce |delta|; last CTA finalizes the step ----
    #pragma unroll
    for (int off = 16; off > 0; off >>= 1)
        lsum += __shfl_xor_sync(0xFFFFFFFFu, lsum, off);
    if (lane == 0) sred[wwid] = lsum;
    __syncthreads();
    if (tid == 0) {
        float bs = 0.0f;
        #pragma unroll
        for (int i = 0; i < 8; i++) bs += sred[i];
        atomicAdd(&g_sum, (double)bs);
        __threadfence();
        unsigned prev = atomicAdd(&g_count, 1u);
        if (prev == NBLK - 1) {
            __threadfence();
            double mean = g_sum / (double)FIELD_N;
            g_steps += 1;
            if (mean < THRESH_C) g_done = 1;
            g_cur ^= 1;
            g_sum = 0.0;
            g_count = 0u;
            __threadfence();
        }
    }
}

__global__ void afe_output_kernel(float* __restrict__ out, int out_size) {
    const float* f = g_cur ? g_buf1 : g_buf0;
    int tid = blockIdx.x * blockDim.x + threadIdx.x;
    int stride = gridDim.x * blockDim.x;
    float stepsf = (float)g_steps;
    for (int i = tid; i < out_size; i += stride)
        out[i] = (i < FIELD_N) ? f[i] : stepsf;
}

extern "C" void kernel_launch(void* const* d_in, const int* in_sizes, int n_in,
                              void* d_out, int out_size) {
    const float* field  = (const float*)d_in[0];
    const float* dw     = (const float*)d_in[1];
    const float* db     = (const float*)d_in[2];
    const float* w1     = (const float*)d_in[3];
    const float* b1     = (const float*)d_in[4];
    const float* w2     = (const float*)d_in[5];
    const float* b2     = (const float*)d_in[6];
    const float* dcoeff = (const float*)d_in[7];

    cudaFuncSetAttribute(afe_step_kernel,
                         cudaFuncAttributeMaxDynamicSharedMemorySize, SMEM_BYTES);

    afe_init_kernel<<<1024, 256>>>(field);
    afe_prep_weights<<<64, 256>>>(w1, w2);

    dim3 grid(W / TILE_W, H / TILE_H, BB);  // (8, 16, 4) = 512 CTAs
    for (int s = 0; s < MAX_STEPS; s++) {
        afe_step_kernel<<<grid, NT, SMEM_BYTES>>>(dw, db, b1, b2, dcoeff);
    }

    afe_output_kernel<<<2048, 256>>>((float*)d_out, out_size);
}

// round 8
// speedup vs baseline: 1.2450x; 1.0952x over previous
#include <cuda_runtime.h>
#include <cuda_bf16.h>
#include <math.h>

#define BB 4
#define C 64
#define C2 128
#define H 128
#define W 128
#define HW (H*W)
#define FIELD_N (BB*C*HW)
#define TILE_H 8
#define TILE_W 16
#define NT 256
#define NBLK 512
#define MAX_STEPS 50
#define DT_C 0.1f
#define THRESH_C 0.01

// ---- smem byte offsets ----
#define SM_SF   0          // 64*180*4 = 46080 fp32 halo
#define SM_W1Q  46080      // 32768 (128 rows x 16 uint4 entries)
#define SM_W2Q  78848      // 32768 (64 rows x 32 uint4 entries)
#define SM_B1   111616     // 512
#define SM_B2   112128     // 256  (prescaled)
#define SM_DW   112640     // 2304 (prescaled)
#define SM_RED  114944     // 32
#define SMEM_BYTES 114976

typedef unsigned u32;
typedef unsigned short u16;

__device__ __forceinline__ u32 pack_bf16x2(float lo, float hi) {
    __nv_bfloat162 t = __floats2bfloat162_rn(lo, hi);
    return *reinterpret_cast<u32*>(&t);
}

__device__ __forceinline__ void mma_bf16(float* d, const u32* a, u32 b0, u32 b1) {
    asm volatile(
        "mma.sync.aligned.m16n8k16.row.col.f32.bf16.bf16.f32 "
        "{%0,%1,%2,%3}, {%4,%5,%6,%7}, {%8,%9}, {%0,%1,%2,%3};"
        : "+f"(d[0]), "+f"(d[1]), "+f"(d[2]), "+f"(d[3])
        : "r"(a[0]), "r"(a[1]), "r"(a[2]), "r"(a[3]), "r"(b0), "r"(b1));
}

// gelu(x) with A&S 7.1.26 erf approximation, |erf err| <= 1.5e-7 abs
__device__ __forceinline__ float gelu_f(float x) {
    float ax = fabsf(x) * 0.70710678118654752f;
    float t = __fdividef(1.0f, fmaf(0.3275911f, ax, 1.0f));
    float poly = t * fmaf(t, fmaf(t, fmaf(t, fmaf(t, 1.061405429f, -1.453152027f),
                                          1.421413741f), -0.284496736f), 0.254829592f);
    float e = __expf(-ax * ax);
    float er = fmaf(-poly, e, 1.0f);
    er = copysignf(er, x);
    return 0.5f * x * (1.0f + er);
}

__device__ float g_buf0[FIELD_N];
__device__ float g_buf1[FIELD_N];
__device__ int      g_done;
__device__ int      g_steps;
__device__ int      g_cur;
__device__ double   g_sum;
__device__ unsigned g_count;
// combined uint4 weight entries {bh0, bh1, bl0, bl1}, phase-swizzled
__device__ __align__(16) u32 g_w1q[8192];
__device__ __align__(16) u32 g_w2q[8192];
__device__ float g_dws[C * 9];   // DT*dc*dw
__device__ float g_b2s[C];       // DT*(dc*db + b2)

__global__ void afe_init_kernel(const float* __restrict__ field) {
    int tid = blockIdx.x * blockDim.x + threadIdx.x;
    if (tid == 0) { g_done = 0; g_steps = 0; g_cur = 0; g_sum = 0.0; g_count = 0u; }
    int stride = gridDim.x * blockDim.x;
    for (int i = tid; i < FIELD_N; i += stride) g_buf0[i] = field[i];
}

__global__ void afe_prep_weights(const float* __restrict__ w1, const float* __restrict__ w2,
                                 const float* __restrict__ dw, const float* __restrict__ db,
                                 const float* __restrict__ b2, const float* __restrict__ dcoeff) {
    int tid = blockIdx.x * blockDim.x + threadIdx.x;
    int stride = gridDim.x * blockDim.x;
    float dc = dcoeff[0];
    // W1 [j=128][word w=0..31], word w covers c = 2w, 2w+1; w = 8kc + t4 + 4q
    for (int i = tid; i < C2 * 32; i += stride) {
        int j = i >> 5, w = i & 31;
        int kc = w >> 3, rem = w & 7;
        int q = rem >> 2, t4 = rem & 3;
        int c = 2 * w;
        float v0 = w1[j * C + c], v1 = w1[j * C + c + 1];
        __nv_bfloat16 h0 = __float2bfloat16_rn(v0), h1 = __float2bfloat16_rn(v1);
        float l0 = v0 - __bfloat162float(h0), l1 = v1 - __bfloat162float(h1);
        int e_log = kc * 4 + t4;
        int e_phys = e_log ^ ((j & 1) << 2);
        int idx = j * 64 + e_phys * 4 + q;
        g_w1q[idx]     = pack_bf16x2(__bfloat162float(h0), __bfloat162float(h1));
        g_w1q[idx + 2] = pack_bf16x2(l0, l1);
    }
    // W2 [c=64][word w=0..63], word w covers j = 2w, 2w+1; w = 8kc + t4 + 4q
    for (int i = tid; i < C * 64; i += stride) {
        int cc = i >> 6, w = i & 63;
        int kc = w >> 3, rem = w & 7;
        int q = rem >> 2, t4 = rem & 3;
        int j = 2 * w;
        float v0 = w2[cc * C2 + j], v1 = w2[cc * C2 + j + 1];
        __nv_bfloat16 h0 = __float2bfloat16_rn(v0), h1 = __float2bfloat16_rn(v1);
        float l0 = v0 - __bfloat162float(h0), l1 = v1 - __bfloat162float(h1);
        int e_log = kc * 4 + t4;
        int e_phys = e_log ^ ((cc & 1) << 2);
        int idx = cc * 128 + e_phys * 4 + q;
        g_w2q[idx]     = pack_bf16x2(__bfloat162float(h0), __bfloat162float(h1));
        g_w2q[idx + 2] = pack_bf16x2(l0, l1);
    }
    // prescaled depthwise weights and bias
    for (int i = tid; i < C * 9; i += stride) g_dws[i] = DT_C * dc * dw[i];
    for (int i = tid; i < C; i += stride)     g_b2s[i] = DT_C * fmaf(dc, db[i], b2[i]);
}

__global__ __launch_bounds__(NT, 2)
void afe_step_kernel(const float* __restrict__ b1) {
    if (g_done) return;

    extern __shared__ char smc[];
    float* sf  = (float*)(smc + SM_SF);
    u32* sW1q = (u32*)(smc + SM_W1Q);
    u32* sW2q = (u32*)(smc + SM_W2Q);
    float* sb1 = (float*)(smc + SM_B1);
    float* sb2 = (float*)(smc + SM_B2);
    float* sdw = (float*)(smc + SM_DW);
    float* sred = (float*)(smc + SM_RED);

    const float* fin  = g_cur ? g_buf1 : g_buf0;
    float*       fout = g_cur ? g_buf0 : g_buf1;

    const int b  = blockIdx.z;
    const int y0 = blockIdx.y * TILE_H;
    const int x0 = blockIdx.x * TILE_W;
    const int tid = threadIdx.x;
    const int wwid = tid >> 5;
    const int lane = tid & 31;
    const int g2 = lane >> 2;
    const int t4 = lane & 3;

    // ---- stage weights (linear uint4 copies) ----
    {
        uint4* d0 = (uint4*)sW1q; const uint4* s0 = (const uint4*)g_w1q;
        uint4* d1 = (uint4*)sW2q; const uint4* s1 = (const uint4*)g_w2q;
        #pragma unroll
        for (int i = tid; i < 2048; i += NT) { d0[i] = s0[i]; d1[i] = s1[i]; }
    }
    if (tid < C2) sb1[tid] = b1[tid];
    if (tid < C)  sb2[tid] = g_b2s[tid];
    for (int i = tid; i < C * 9; i += NT) sdw[i] = g_dws[i];

    // ---- fp32 halo tile [64][10][18], zero-pad SAME; incremental indexing ----
    {
        int c  = tid / 180;
        int rem = tid - c * 180;
        int rr = rem / 18;
        int xx = rem - rr * 18;
        int i = tid;
        #pragma unroll 5
        for (int it = 0; it < 45; it++) {
            int y = y0 - 1 + rr;
            int x = x0 - 1 + xx;
            float v = 0.0f;
            if ((unsigned)y < H && (unsigned)x < W)
                v = fin[((b * C + c) * H + y) * W + x];
            sf[i] = v;
            // advance by 256 = 1*180 + 4*18 + 4
            i += 256; c += 1; rr += 4; xx += 4;
            if (xx >= 18) { xx -= 18; rr += 1; }
            if (rr >= 10) { rr -= 10; c += 1; }
        }
    }
    __syncthreads();

    // ---- A1 fragments in registers straight from sf ----
    u32 ah[4][4], al[4][4];
    {
        const int pr = (wwid + 1) * 18 + 1;
        #pragma unroll
        for (int kc = 0; kc < 4; kc++) {
            #pragma unroll
            for (int q = 0; q < 2; q++) {
                int c = 16 * kc + 2 * t4 + 8 * q;
                float v00 = sf[c * 180 + pr + g2];
                float v01 = sf[(c + 1) * 180 + pr + g2];
                float v10 = sf[c * 180 + pr + g2 + 8];
                float v11 = sf[(c + 1) * 180 + pr + g2 + 8];
                __nv_bfloat16 h00 = __float2bfloat16_rn(v00);
                __nv_bfloat16 h01 = __float2bfloat16_rn(v01);
                __nv_bfloat16 h10 = __float2bfloat16_rn(v10);
                __nv_bfloat16 h11 = __float2bfloat16_rn(v11);
                ah[kc][2 * q]     = pack_bf16x2(__bfloat162float(h00), __bfloat162float(h01));
                ah[kc][2 * q + 1] = pack_bf16x2(__bfloat162float(h10), __bfloat162float(h11));
                al[kc][2 * q]     = pack_bf16x2(v00 - __bfloat162float(h00), v01 - __bfloat162float(h01));
                al[kc][2 * q + 1] = pack_bf16x2(v10 - __bfloat162float(h10), v11 - __bfloat162float(h11));
            }
        }
    }

    // ---- GEMM1 (two N-halves) + gelu -> GEMM2 A fragments ----
    u32 a2h[8][4], a2l[8][4];
    #pragma unroll
    for (int hh = 0; hh < 2; hh++) {
        float acc[8][4];
        #pragma unroll
        for (int ntl = 0; ntl < 8; ntl++)
            #pragma unroll
            for (int e = 0; e < 4; e++) acc[ntl][e] = 0.0f;

        #pragma unroll
        for (int ntl = 0; ntl < 8; ntl++) {
            const int row = 8 * (8 * hh + ntl) + g2;
            const int rbase = row * 64;
            const int rsw = (row & 1) << 2;
            #pragma unroll
            for (int kc = 0; kc < 4; kc++) {
                int off = rbase + (((kc * 4 + t4) ^ rsw) << 2);
                uint4 wq = *(const uint4*)(sW1q + off);
                mma_bf16(acc[ntl], ah[kc], wq.x, wq.y);
                mma_bf16(acc[ntl], ah[kc], wq.z, wq.w);
                mma_bf16(acc[ntl], al[kc], wq.x, wq.y);
            }
        }

        #pragma unroll
        for (int ntl = 0; ntl < 8; ntl++) {
            const int n = 8 * hh + ntl;
            float bias0 = sb1[8 * n + 2 * t4];
            float bias1 = sb1[8 * n + 2 * t4 + 1];
            float gl0 = gelu_f(acc[ntl][0] + bias0);
            float gl1 = gelu_f(acc[ntl][1] + bias1);
            float gl2 = gelu_f(acc[ntl][2] + bias0);
            float gl3 = gelu_f(acc[ntl][3] + bias1);
            __nv_bfloat16 h0 = __float2bfloat16_rn(gl0);
            __nv_bfloat16 h1 = __float2bfloat16_rn(gl1);
            __nv_bfloat16 h2 = __float2bfloat16_rn(gl2);
            __nv_bfloat16 h3 = __float2bfloat16_rn(gl3);
            int kc2 = n >> 1;
            int q  = (n & 1) << 1;
            a2h[kc2][q]     = pack_bf16x2(__bfloat162float(h0), __bfloat162float(h1));
            a2h[kc2][q + 1] = pack_bf16x2(__bfloat162float(h2), __bfloat162float(h3));
            a2l[kc2][q]     = pack_bf16x2(gl0 - __bfloat162float(h0), gl1 - __bfloat162float(h1));
            a2l[kc2][q + 1] = pack_bf16x2(gl2 - __bfloat162float(h2), gl3 - __bfloat162float(h3));
        }
    }

    // ---- GEMM2 ----
    float acc2[8][4];
    #pragma unroll
    for (int nt = 0; nt < 8; nt++)
        #pragma unroll
        for (int e = 0; e < 4; e++) acc2[nt][e] = 0.0f;

    #pragma unroll
    for (int nt = 0; nt < 8; nt++) {
        const int row = 8 * nt + g2;
        const int rbase = row * 128;
        const int rsw = (row & 1) << 2;
        #pragma unroll
        for (int kc = 0; kc < 8; kc++) {
            int off = rbase + (((kc * 4 + t4) ^ rsw) << 2);
            uint4 wq = *(const uint4*)(sW2q + off);
            mma_bf16(acc2[nt], a2h[kc], wq.x, wq.y);
            mma_bf16(acc2[nt], a2h[kc], wq.z, wq.w);
            mma_bf16(acc2[nt], a2l[kc], wq.x, wq.y);
        }
    }

    // ---- epilogue: depthwise (prescaled) + Euler + |delta| ----
    float lsum = 0.0f;
    #pragma unroll
    for (int nt = 0; nt < 8; nt++) {
        #pragma unroll
        for (int e = 0; e < 2; e++) {
            const int c = 8 * nt + 2 * t4 + e;
            const float* base = sf + c * 180;
            const float wd0 = sdw[c * 9 + 0], wd1 = sdw[c * 9 + 1], wd2 = sdw[c * 9 + 2];
            const float wd3 = sdw[c * 9 + 3], wd4 = sdw[c * 9 + 4], wd5 = sdw[c * 9 + 5];
            const float wd6 = sdw[c * 9 + 6], wd7 = sdw[c * 9 + 7], wd8 = sdw[c * 9 + 8];
            const float b2v = sb2[c];
            #pragma unroll
            for (int half = 0; half < 2; half++) {
                const int col = g2 + 8 * half;
                float s = b2v;
                s = fmaf(wd0, base[(wwid + 0) * 18 + col + 0], s);
                s = fmaf(wd1, base[(wwid + 0) * 18 + col + 1], s);
                s = fmaf(wd2, base[(wwid + 0) * 18 + col + 2], s);
                s = fmaf(wd3, base[(wwid + 1) * 18 + col + 0], s);
                s = fmaf(wd4, base[(wwid + 1) * 18 + col + 1], s);
                s = fmaf(wd5, base[(wwid + 1) * 18 + col + 2], s);
                s = fmaf(wd6, base[(wwid + 2) * 18 + col + 0], s);
                s = fmaf(wd7, base[(wwid + 2) * 18 + col + 1], s);
                s = fmaf(wd8, base[(wwid + 2) * 18 + col + 2], s);
                s = fmaf(DT_C, acc2[nt][2 * half + e], s);
                float fold = base[(wwid + 1) * 18 + col + 1];
                float fnew = fold + s;
                lsum += fabsf(s);
                fout[((b * C + c) * H + (y0 + wwid)) * W + (x0 + col)] = fnew;
            }
        }
    }

    // ---- reduce |delta|; last CTA finalizes the step ----
    #pragma unroll
    for (int off = 16; off > 0; off >>= 1)
        lsum += __shfl_xor_sync(0xFFFFFFFFu, lsum, off);
    if (lane == 0) sred[wwid] = lsum;
    __syncthreads();
    if (tid == 0) {
        float bs = 0.0f;
        #pragma unroll
        for (int i = 0; i < 8; i++) bs += sred[i];
        atomicAdd(&g_sum, (double)bs);
        __threadfence();
        unsigned prev = atomicAdd(&g_count, 1u);
        if (prev == NBLK - 1) {
            __threadfence();
            double mean = g_sum / (double)FIELD_N;
            g_steps += 1;
            if (mean < THRESH_C) g_done = 1;
            g_cur ^= 1;
            g_sum = 0.0;
            g_count = 0u;
            __threadfence();
        }
    }
}

__global__ void afe_output_kernel(float* __restrict__ out, int out_size) {
    const float* f = g_cur ? g_buf1 : g_buf0;
    int tid = blockIdx.x * blockDim.x + threadIdx.x;
    int stride = gridDim.x * blockDim.x;
    float stepsf = (float)g_steps;
    for (int i = tid; i < out_size; i += stride)
        out[i] = (i < FIELD_N) ? f[i] : stepsf;
}

extern "C" void kernel_launch(void* const* d_in, const int* in_sizes, int n_in,
                              void* d_out, int out_size) {
    const float* field  = (const float*)d_in[0];
    const float* dw     = (const float*)d_in[1];
    const float* db     = (const float*)d_in[2];
    const float* w1     = (const float*)d_in[3];
    const float* b1     = (const float*)d_in[4];
    const float* w2     = (const float*)d_in[5];
    const float* b2     = (const float*)d_in[6];
    const float* dcoeff = (const float*)d_in[7];

    cudaFuncSetAttribute(afe_step_kernel,
                         cudaFuncAttributeMaxDynamicSharedMemorySize, SMEM_BYTES);

    afe_init_kernel<<<1024, 256>>>(field);
    afe_prep_weights<<<64, 256>>>(w1, w2, dw, db, b2, dcoeff);

    dim3 grid(W / TILE_W, H / TILE_H, BB);  // (8, 16, 4) = 512 CTAs
    for (int s = 0; s < MAX_STEPS; s++) {
        afe_step_kernel<<<grid, NT, SMEM_BYTES>>>(b1);
    }

    afe_output_kernel<<<2048, 256>>>((float*)d_out, out_size);
}